// round 4
// baseline (speedup 1.0000x reference)
#include <cuda_runtime.h>
#include <cstdint>
#include <math.h>

#define B_SZ 16384
#define H_SZ 512
#define G4   2048
#define OUTF 256
#define KPAD 288
#define IN0  257
#define MB   128          // row-blocks along batch = B/128

// ---------------- scratch (static device memory) ------------------------------
__device__ float g_inp [(size_t)B_SZ * KPAD];   // tf32, k-permuted concat(x,y) padded
__device__ float g_WxP [(size_t)G4 * KPAD];     // tf32, k-permuted padded Wx0
__device__ float g_Zx  [(size_t)B_SZ * G4];
__device__ float g_Zh  [(size_t)B_SZ * G4];
__device__ float g_h00t[(size_t)B_SZ * H_SZ];
__device__ float g_h01t[(size_t)B_SZ * H_SZ];
__device__ float g_h1t [(size_t)B_SZ * H_SZ];
__device__ float g_h2t [(size_t)B_SZ * H_SZ];
__device__ float g_Wh0t[(size_t)G4 * H_SZ];
__device__ float g_Wx1t[(size_t)G4 * H_SZ];
__device__ float g_Wh1t[(size_t)G4 * H_SZ];
__device__ float g_Wot [(size_t)OUTF * H_SZ];
__device__ float g_partX[(size_t)MB * G4 * 2];  // per-rowblock col (sum, sumsq)
__device__ float g_partH[(size_t)MB * G4 * 2];
__device__ float g_scX[G4], g_shX[G4], g_scH[G4], g_shH[G4];

// ---------------- helpers ------------------------------------------------------
__device__ __forceinline__ uint32_t f2tf(float f) {
    uint32_t u = __float_as_uint(f);
    uint32_t r = u + 0xFFFu + ((u >> 13) & 1u);   // RNE to tf32
    return r & 0xFFFFE000u;
}
__device__ __forceinline__ float sigm(float x) { return 1.f / (1.f + expf(-x)); }

// k-permutation within each 8-group: phys pos p holds logical k(p) = (p>>1) + ((p&1)<<2)
__device__ __forceinline__ int kofp(int p) { return (p >> 1) + ((p & 1) << 2); }

// ---------------- conversion / prep kernels -----------------------------------
__global__ void prep_inp(const float* __restrict__ x, const float* __restrict__ y) {
    int i = blockIdx.x * blockDim.x + threadIdx.x;        // B*KPAD
    int b = i / KPAD, pc = i - b * KPAD;
    int j = (pc & ~7) + kofp(pc & 7);
    float v = (j < 256) ? x[(size_t)b * 256 + j] : (j == IN0 - 1 ? y[b] : 0.f);
    g_inp[i] = __uint_as_float(f2tf(v));
}
__global__ void prep_wx(const float* __restrict__ Wx) {
    int i = blockIdx.x * blockDim.x + threadIdx.x;        // G4*KPAD
    int r = i / KPAD, pc = i - r * KPAD;
    int j = (pc & ~7) + kofp(pc & 7);
    float v = (j < IN0) ? Wx[(size_t)r * IN0 + j] : 0.f;
    g_WxP[i] = __uint_as_float(f2tf(v));
}
__global__ void conv_perm(float* __restrict__ dst, const float* __restrict__ src, int n) {
    int i = blockIdx.x * blockDim.x + threadIdx.x;
    if (i >= n) return;
    int j = (i & ~7) + kofp(i & 7);
    dst[i] = __uint_as_float(f2tf(src[j]));
}

// ---------------- tf32 mma GEMM: C[M,N] = A[M,K] * W[N,K]^T (+bias) ------------
// block 128x256, BK=32, 8 warps (2x4), warp tile 64x64, cp.async double buffer.
// Inputs are pre-rounded tf32 with per-8-group k-permutation so fragment loads are LDS.64.
constexpr int BM = 128, BN = 256, BK = 32;
constexpr int STG = (BM + BN) * BK;   // floats per stage = 12288 (48 KB)

__device__ __forceinline__ void cpasync16(uint32_t dst, const void* src) {
    asm volatile("cp.async.cg.shared.global [%0], [%1], 16;\n" :: "r"(dst), "l"(src));
}

__global__ __launch_bounds__(256, 1) void gemm_tn(
    float* __restrict__ C, const float* __restrict__ A, int lda,
    const float* __restrict__ W, int ldw, int N, int K,
    const float* __restrict__ bias, float* __restrict__ part)
{
    extern __shared__ float sm[];
    const int tid  = threadIdx.x;
    const int lane = tid & 31, warp = tid >> 5;
    const int g    = lane >> 2, tg = lane & 3;
    const int wm   = warp >> 2, wn = warp & 3;
    const int mW   = wm * 64, nW = wn * 64;
    const int bM   = blockIdx.y * BM, bN = blockIdx.x * BN;
    const uint32_t smB = (uint32_t)__cvta_generic_to_shared(sm);

    float acc[4][8][4];
#pragma unroll
    for (int a = 0; a < 4; a++)
#pragma unroll
        for (int b = 0; b < 8; b++)
#pragma unroll
            for (int c = 0; c < 4; c++) acc[a][b][c] = 0.f;

    auto load_stage = [&](int st, int k0) {
        uint32_t base = smB + (uint32_t)(st * STG * 4);
#pragma unroll
        for (int i = 0; i < 4; i++) {                 // A tile: 128x32
            int u = tid + i * 256, row = u >> 3, ch = u & 7;
            const float* src = A + (size_t)(bM + row) * lda + k0 + ch * 4;
            uint32_t dst = base + (uint32_t)(((((ch >> 1) * BM + row) << 3) + (ch & 1) * 4) * 4);
            cpasync16(dst, src);
        }
#pragma unroll
        for (int i = 0; i < 8; i++) {                 // W tile: 256x32
            int u = tid + i * 256, row = u >> 3, ch = u & 7;
            const float* src = W + (size_t)(bN + row) * ldw + k0 + ch * 4;
            uint32_t dst = base + (uint32_t)((BM * BK + ((((ch >> 1) * BN + row) << 3) + (ch & 1) * 4)) * 4);
            cpasync16(dst, src);
        }
    };

    auto compute = [&](int st) {
        const float* sA = sm + st * STG;
        const float* sW = sm + st * STG + BM * BK;
#pragma unroll
        for (int kb = 0; kb < 4; kb++) {
            uint2 bf[8];
#pragma unroll
            for (int nt = 0; nt < 8; nt++)
                bf[nt] = *(const uint2*)&sW[((kb * BN + nW + nt * 8 + g) << 3) + 2 * tg];
            uint2 a02[4], a13[4];
#pragma unroll
            for (int mt = 0; mt < 4; mt++) {
                int r0 = mW + mt * 16 + g;
                a02[mt] = *(const uint2*)&sA[((kb * BM + r0) << 3) + 2 * tg];
                a13[mt] = *(const uint2*)&sA[((kb * BM + r0 + 8) << 3) + 2 * tg];
            }
#pragma unroll
            for (int mt = 0; mt < 4; mt++)
#pragma unroll
                for (int nt = 0; nt < 8; nt++)
                    asm volatile(
                        "mma.sync.aligned.m16n8k8.row.col.f32.tf32.tf32.f32 "
                        "{%0,%1,%2,%3},{%4,%5,%6,%7},{%8,%9},{%0,%1,%2,%3};\n"
                        : "+f"(acc[mt][nt][0]), "+f"(acc[mt][nt][1]),
                          "+f"(acc[mt][nt][2]), "+f"(acc[mt][nt][3])
                        : "r"(a02[mt].x), "r"(a13[mt].x), "r"(a02[mt].y), "r"(a13[mt].y),
                          "r"(bf[nt].x), "r"(bf[nt].y));
        }
    };

    const int nit = K >> 5;
    load_stage(0, 0);
    asm volatile("cp.async.commit_group;\n");
    for (int it = 0; it < nit; ++it) {
        if (it + 1 < nit) {
            load_stage((it + 1) & 1, (it + 1) << 5);
            asm volatile("cp.async.commit_group;\n");
            asm volatile("cp.async.wait_group 1;\n");
        } else {
            asm volatile("cp.async.wait_group 0;\n");
        }
        __syncthreads();
        compute(it & 1);
        __syncthreads();
    }

    // ---- write C tile ----
#pragma unroll
    for (int mt = 0; mt < 4; mt++) {
        int r0 = bM + mW + mt * 16 + g;
#pragma unroll
        for (int nt = 0; nt < 8; nt++) {
            int c = bN + nW + nt * 8 + 2 * tg;
            float b0 = 0.f, b1 = 0.f;
            if (bias) { b0 = bias[c]; b1 = bias[c + 1]; }
            *(float2*)&C[(size_t)r0 * N + c]       = make_float2(acc[mt][nt][0] + b0, acc[mt][nt][1] + b1);
            *(float2*)&C[(size_t)(r0 + 8) * N + c] = make_float2(acc[mt][nt][2] + b0, acc[mt][nt][3] + b1);
        }
    }

    // ---- fused BN statistics: per-block column (sum, sumsq) partials ----
    if (part) {
        __syncthreads();                   // pipeline smem now reusable
        float* psm = sm;                   // [2 wm][256 col][2]
#pragma unroll
        for (int nt = 0; nt < 8; nt++) {
            float s0 = 0.f, q0 = 0.f, s1 = 0.f, q1 = 0.f;
#pragma unroll
            for (int mt = 0; mt < 4; mt++) {
                float v0 = acc[mt][nt][0], v2 = acc[mt][nt][2];
                float v1 = acc[mt][nt][1], v3 = acc[mt][nt][3];
                s0 += v0 + v2; q0 += v0 * v0 + v2 * v2;
                s1 += v1 + v3; q1 += v1 * v1 + v3 * v3;
            }
#pragma unroll
            for (int off = 16; off >= 4; off >>= 1) {
                s0 += __shfl_xor_sync(0xFFFFFFFFu, s0, off);
                q0 += __shfl_xor_sync(0xFFFFFFFFu, q0, off);
                s1 += __shfl_xor_sync(0xFFFFFFFFu, s1, off);
                q1 += __shfl_xor_sync(0xFFFFFFFFu, q1, off);
            }
            if (g == 0) {
                int col = nW + nt * 8 + 2 * tg;
                psm[(wm * 256 + col) * 2 + 0]     = s0;
                psm[(wm * 256 + col) * 2 + 1]     = q0;
                psm[(wm * 256 + col + 1) * 2 + 0] = s1;
                psm[(wm * 256 + col + 1) * 2 + 1] = q1;
            }
        }
        __syncthreads();
#pragma unroll
        for (int i = 0; i < 2; i++) {
            int e = tid + i * 256;                 // 512 entries = 256 cols x {s,q}
            int col = e >> 1, sq = e & 1;
            float v = psm[col * 2 + sq] + psm[(256 + col) * 2 + sq];
            part[((size_t)blockIdx.y * N + bN + col) * 2 + sq] = v;
        }
    }
}

// ---------------- fold partials into BN affine scale/shift ---------------------
__global__ void stats_final(const float* __restrict__ gx, const float* __restrict__ bx,
                            const float* __restrict__ gh, const float* __restrict__ bh) {
    int j = blockIdx.x * blockDim.x + threadIdx.x;     // 2048
    float sx = 0.f, qx = 0.f, sh = 0.f, qh = 0.f;
    for (int rb = 0; rb < MB; rb++) {
        size_t o = ((size_t)rb * G4 + j) * 2;
        sx += g_partX[o]; qx += g_partX[o + 1];
        sh += g_partH[o]; qh += g_partH[o + 1];
    }
    const float invB = 1.f / (float)B_SZ;
    float mx = sx * invB, vx = qx * invB - mx * mx;
    float ax = gx[j] * rsqrtf(vx + 1e-5f);
    g_scX[j] = ax; g_shX[j] = bx[j] - mx * ax;
    float mh = sh * invB, vh = qh * invB - mh * mh;
    float ah = gh[j] * rsqrtf(vh + 1e-5f);
    g_scH[j] = ah; g_shH[j] = bh[j] - mh * ah;
}

// ---------------- fused BN + LSTM cell + tf32/perm h export --------------------
__global__ void cell_kernel(const float* __restrict__ Zx, const float* __restrict__ Zh,
                            const float* __restrict__ cPrev,
                            float* __restrict__ hOut, float* __restrict__ hT,
                            float* __restrict__ cOut) {
    int idx = blockIdx.x * blockDim.x + threadIdx.x;   // B*512
    int j = idx & 511, b = idx >> 9;
    size_t base = ((size_t)b << 11) + j;
    float zf = Zx[base       ] * g_scX[j       ] + g_shX[j       ] + Zh[base       ] * g_scH[j       ] + g_shH[j       ];
    float zi = Zx[base +  512] * g_scX[j +  512] + g_shX[j +  512] + Zh[base +  512] * g_scH[j +  512] + g_shH[j +  512];
    float zo = Zx[base + 1024] * g_scX[j + 1024] + g_shX[j + 1024] + Zh[base + 1024] * g_scH[j + 1024] + g_shH[j + 1024];
    float zg = Zx[base + 1536] * g_scX[j + 1536] + g_shX[j + 1536] + Zh[base + 1536] * g_scH[j + 1536] + g_shH[j + 1536];
    float c2 = sigm(zf) * cPrev[idx] + sigm(zi) * tanhf(zg);
    float h  = sigm(zo) * tanhf(c2);
    hOut[idx] = h; cOut[idx] = c2;
    int w = j & 7, p = ((w & 3) << 1) | (w >> 2);       // inverse of kofp
    hT[((size_t)b << 9) + (j & ~7) + p] = __uint_as_float(f2tf(h));
}

// ---------------- launch -------------------------------------------------------
extern "C" void kernel_launch(void* const* d_in, const int* in_sizes, int n_in,
                              void* d_out, int out_size) {
    const float* x   = (const float*)d_in[0];
    const float* y   = (const float*)d_in[1];
    const float* h0  = (const float*)d_in[2];
    const float* c0  = (const float*)d_in[3];
    const float* Wx0 = (const float*)d_in[4];
    const float* Wh0 = (const float*)d_in[5];
    const float* gx0 = (const float*)d_in[6];
    const float* bx0 = (const float*)d_in[7];
    const float* gh0 = (const float*)d_in[8];
    const float* bh0 = (const float*)d_in[9];
    const float* Wx1 = (const float*)d_in[10];
    const float* Wh1 = (const float*)d_in[11];
    const float* gx1 = (const float*)d_in[12];
    const float* bx1 = (const float*)d_in[13];
    const float* gh1 = (const float*)d_in[14];
    const float* bh1 = (const float*)d_in[15];
    const float* Wo  = (const float*)d_in[16];
    const float* bo  = (const float*)d_in[17];
    float* out = (float*)d_out;

    cudaFuncSetAttribute(gemm_tn, cudaFuncAttributeMaxDynamicSharedMemorySize, 2 * STG * 4);

    float *inp, *wxp, *Zx, *Zh, *h00t, *h01t, *h1t, *h2t, *Wh0t, *Wx1t, *Wh1t, *Wot, *partX, *partH;
    cudaGetSymbolAddress((void**)&inp,   g_inp);
    cudaGetSymbolAddress((void**)&wxp,   g_WxP);
    cudaGetSymbolAddress((void**)&Zx,    g_Zx);
    cudaGetSymbolAddress((void**)&Zh,    g_Zh);
    cudaGetSymbolAddress((void**)&h00t,  g_h00t);
    cudaGetSymbolAddress((void**)&h01t,  g_h01t);
    cudaGetSymbolAddress((void**)&h1t,   g_h1t);
    cudaGetSymbolAddress((void**)&h2t,   g_h2t);
    cudaGetSymbolAddress((void**)&Wh0t,  g_Wh0t);
    cudaGetSymbolAddress((void**)&Wx1t,  g_Wx1t);
    cudaGetSymbolAddress((void**)&Wh1t,  g_Wh1t);
    cudaGetSymbolAddress((void**)&Wot,   g_Wot);
    cudaGetSymbolAddress((void**)&partX, g_partX);
    cudaGetSymbolAddress((void**)&partH, g_partH);

    // output layout: out[B,256], h1[B,512], h2[B,512], c1[B,512], c2[B,512]
    float* h1 = out + (size_t)B_SZ * OUTF;
    float* h2 = h1 + (size_t)B_SZ * H_SZ;
    float* c1 = h2 + (size_t)B_SZ * H_SZ;
    float* c2 = c1 + (size_t)B_SZ * H_SZ;
    const float* h00 = h0;
    const float* h01 = h0 + (size_t)B_SZ * H_SZ;
    const float* c00 = c0;
    const float* c01 = c0 + (size_t)B_SZ * H_SZ;

    const int BH = B_SZ * H_SZ;
    const int GH = G4 * H_SZ;

    prep_inp<<<(B_SZ * KPAD) / 256, 256>>>(x, y);
    prep_wx<<<(G4 * KPAD) / 256, 256>>>(Wx0);
    conv_perm<<<BH / 256, 256>>>(h00t, h00, BH);
    conv_perm<<<BH / 256, 256>>>(h01t, h01, BH);
    conv_perm<<<GH / 256, 256>>>(Wh0t, Wh0, GH);
    conv_perm<<<GH / 256, 256>>>(Wx1t, Wx1, GH);
    conv_perm<<<GH / 256, 256>>>(Wh1t, Wh1, GH);
    conv_perm<<<(OUTF * H_SZ) / 256, 256>>>(Wot, Wo, OUTF * H_SZ);

    dim3 gg(G4 / BN, B_SZ / BM);     // 8 x 128
    dim3 go(OUTF / BN, B_SZ / BM);   // 1 x 128
    size_t smem = 2 * STG * 4;

    // layer 0
    gemm_tn<<<gg, 256, smem>>>(Zx, inp,  KPAD, wxp,  KPAD, G4, KPAD, nullptr, partX);
    gemm_tn<<<gg, 256, smem>>>(Zh, h00t, H_SZ, Wh0t, H_SZ, G4, H_SZ, nullptr, partH);
    stats_final<<<G4 / 256, 256>>>(gx0, bx0, gh0, bh0);
    cell_kernel<<<BH / 256, 256>>>(Zx, Zh, c00, h1, h1t, c1);

    // layer 1
    gemm_tn<<<gg, 256, smem>>>(Zx, h1t,  H_SZ, Wx1t, H_SZ, G4, H_SZ, nullptr, partX);
    gemm_tn<<<gg, 256, smem>>>(Zh, h01t, H_SZ, Wh1t, H_SZ, G4, H_SZ, nullptr, partH);
    stats_final<<<G4 / 256, 256>>>(gx1, bx1, gh1, bh1);
    cell_kernel<<<BH / 256, 256>>>(Zx, Zh, c01, h2, h2t, c2);

    // output projection
    gemm_tn<<<go, 256, smem>>>(out, h2t, H_SZ, Wot, H_SZ, OUTF, H_SZ, bo, nullptr);
}